// round 15
// baseline (speedup 1.0000x reference)
#include <cuda_runtime.h>
#include <cuda_fp8.h>
#include <cstdint>
#include <cstddef>

// ============================================================================
// Problem constants
// ============================================================================
#define MDIM 4096
#define KDIM 4096
#define NDIM 11008

// GEMM tiling: CTA 128x128, warp 64x32 (2x4 warps), BK=128, 3-stage cp.async
// SMEM/CTA = 96 KB -> 2 CTAs/SM -> 16 warps/SM.  [R12/R14 config]
// Tail fix: last 88 tiles are split-K=2 (176 half CTAs, one extra wave).
#define BM 128
#define BN 128
#define BK 128                           // fp8 bytes of K per chunk
#define NKCHUNK (KDIM / BK)              // 32
#define STAGES 3
#define A_BYTES (BM * BK)                // 16384
#define B_BYTES (BN * BK)                // 16384
#define STAGE_BYTES (A_BYTES + B_BYTES)  // 32768
#define SMEM_TOTAL (STAGES * STAGE_BYTES)// 98304
#define GEMM_THREADS 256

#define NTILE_N (NDIM / BN)              // 86
#define TOT_TILES 2752                   // 86 * 32
#define FULL_TILES 2664                  // 9 waves x 296 slots
#define SPLIT_TILES (TOT_TILES - FULL_TILES)   // 88
#define GEMM_GRID (FULL_TILES + 2 * SPLIT_TILES) // 2840

#define NPART 2368                        // aux grid size (fixed: partials array)

// ============================================================================
// Scratch (static device globals: allocation-free)
// ============================================================================
__device__ __align__(128) uint8_t g_qin[(size_t)MDIM * KDIM];
__device__ __align__(128) uint8_t g_qw[(size_t)NDIM * KDIM];
__device__ float g_part[2][NPART];       // per-block amax partials
__device__ float g_amax[2];              // final amax (published by quant blk 0)
__device__ int   g_flag[SPLIT_TILES];    // split-K completion flags

// ============================================================================
// Small PTX helpers (base sm_103 features only!)
// ============================================================================
__device__ __forceinline__ uint32_t smem_u32(const void* p) {
    uint32_t a;
    asm("{ .reg .u64 t; cvta.to.shared.u64 t, %1; cvt.u32.u64 %0, t; }"
        : "=r"(a) : "l"(p));
    return a;
}

__device__ __forceinline__ void cp_async16(uint32_t dst, const void* src) {
    asm volatile("cp.async.cg.shared.global [%0], [%1], 16;"
                 :: "r"(dst), "l"(src));
}
#define CP_COMMIT() asm volatile("cp.async.commit_group;" ::: "memory")
#define CP_WAIT1()  asm volatile("cp.async.wait_group 1;" ::: "memory")

__device__ __forceinline__ void ldmatrix_x4(uint32_t& r0, uint32_t& r1,
                                            uint32_t& r2, uint32_t& r3,
                                            uint32_t addr) {
    asm volatile("ldmatrix.sync.aligned.m8n8.x4.shared.b16 {%0,%1,%2,%3}, [%4];"
                 : "=r"(r0), "=r"(r1), "=r"(r2), "=r"(r3) : "r"(addr));
}

__device__ __forceinline__ void mma_fp8(float& d0, float& d1, float& d2, float& d3,
                                        uint32_t a0, uint32_t a1, uint32_t a2, uint32_t a3,
                                        uint32_t b0, uint32_t b1) {
    asm volatile(
        "mma.sync.aligned.m16n8k32.row.col.f32.e4m3.e4m3.f32 "
        "{%0,%1,%2,%3}, {%4,%5,%6,%7}, {%8,%9}, {%0,%1,%2,%3};"
        : "+f"(d0), "+f"(d1), "+f"(d2), "+f"(d3)
        : "r"(a0), "r"(a1), "r"(a2), "r"(a3), "r"(b0), "r"(b1));
}

__device__ __forceinline__ void st_cs_f2(float* p, float2 v) {
    asm volatile("st.global.cs.v2.f32 [%0], {%1, %2};"
                 :: "l"(p), "f"(v.x), "f"(v.y) : "memory");
}

__device__ __forceinline__ float2 ldcg_f2(const float* p) {
    float2 v;
    asm volatile("ld.global.cg.v2.f32 {%0,%1}, [%2];"
                 : "=f"(v.x), "=f"(v.y) : "l"(p));
    return v;
}

__device__ __forceinline__ float4 ldcs_f4(const float4* p) {     // streaming
    float4 v;
    asm volatile("ld.global.cs.v4.f32 {%0,%1,%2,%3}, [%4];"
                 : "=f"(v.x), "=f"(v.y), "=f"(v.z), "=f"(v.w) : "l"(p));
    return v;
}

__device__ __forceinline__ float4 ldca_f4(const float4* p) {     // caching
    float4 v;
    asm volatile("ld.global.ca.v4.f32 {%0,%1,%2,%3}, [%4];"
                 : "=f"(v.x), "=f"(v.y), "=f"(v.z), "=f"(v.w) : "l"(p));
    return v;
}

// ============================================================================
// Block-wide max reduction (order-independent: fmax is assoc/commutative)
// ============================================================================
__device__ __forceinline__ float block_max(float m) {
    #pragma unroll
    for (int o = 16; o; o >>= 1) m = fmaxf(m, __shfl_xor_sync(0xffffffffu, m, o));
    __shared__ float red[8];
    if ((threadIdx.x & 31) == 0) red[threadIdx.x >> 5] = m;
    __syncthreads();
    float r = red[0];
    #pragma unroll
    for (int w = 1; w < 8; w++) r = fmaxf(r, red[w]);
    return r;
}

// ============================================================================
// Phase 1: per-tensor amax -> per-block partials (one launch, gridDim.y=2)
//   Also zeroes the split-K flags (graph replays!).
// ============================================================================
__device__ __forceinline__ float amax4(float4 v) {
    return fmaxf(fmaxf(fabsf(v.x), fabsf(v.y)), fmaxf(fabsf(v.z), fabsf(v.w)));
}

template <int CACHED>
__device__ __forceinline__ void amax_body(const float4* x4, size_t n4, int which) {
    const size_t T = (size_t)NPART * 256;
    const size_t gtid = (size_t)blockIdx.x * blockDim.x + threadIdx.x;
    float m[8];
    #pragma unroll
    for (int k = 0; k < 8; k++) m[k] = 0.0f;
    size_t i = gtid;
    for (; i + 7 * T < n4; i += 8 * T) {
        #pragma unroll
        for (int k = 0; k < 8; k++) {
            float4 v = CACHED ? ldca_f4(&x4[i + k * T]) : ldcs_f4(&x4[i + k * T]);
            m[k] = fmaxf(m[k], amax4(v));
        }
    }
    for (; i < n4; i += T)
        m[0] = fmaxf(m[0], amax4(CACHED ? ldca_f4(&x4[i]) : ldcs_f4(&x4[i])));
    float mm = fmaxf(fmaxf(fmaxf(m[0], m[1]), fmaxf(m[2], m[3])),
                     fmaxf(fmaxf(m[4], m[5]), fmaxf(m[6], m[7])));
    mm = block_max(mm);
    if (threadIdx.x == 0) g_part[which][blockIdx.x] = mm;
}

__global__ void amax_kernel(const float* __restrict__ xin,
                            const float* __restrict__ xw) {
    if (blockIdx.x == 0 && blockIdx.y == 0 && threadIdx.x < SPLIT_TILES)
        g_flag[threadIdx.x] = 0;                 // reset split flags per replay
    if (blockIdx.y == 0)
        amax_body<1>(reinterpret_cast<const float4*>(xin),
                     (size_t)MDIM * KDIM / 4, 0);
    else
        amax_body<0>(reinterpret_cast<const float4*>(xw),
                     (size_t)NDIM * KDIM / 4, 1);
}

// ============================================================================
// Phase 2: quantize BOTH tensors in ONE launch (gridDim.y selects tensor).
// ============================================================================
__device__ __forceinline__ uint32_t q4(float4 v, float s) {
    float a0 = fminf(fmaxf(v.x * s, -448.0f), 448.0f);
    float a1 = fminf(fmaxf(v.y * s, -448.0f), 448.0f);
    float a2 = fminf(fmaxf(v.z * s, -448.0f), 448.0f);
    float a3 = fminf(fmaxf(v.w * s, -448.0f), 448.0f);
    uint32_t b0 = __nv_cvt_float_to_fp8(a0, __NV_SATFINITE, __NV_E4M3);
    uint32_t b1 = __nv_cvt_float_to_fp8(a1, __NV_SATFINITE, __NV_E4M3);
    uint32_t b2 = __nv_cvt_float_to_fp8(a2, __NV_SATFINITE, __NV_E4M3);
    uint32_t b3 = __nv_cvt_float_to_fp8(a3, __NV_SATFINITE, __NV_E4M3);
    return b0 | (b1 << 8) | (b2 << 16) | (b3 << 24);
}

__global__ void quant_kernel(const float* __restrict__ xin,
                             const float* __restrict__ xw) {
    const int which = blockIdx.y;
    const size_t n4 = which ? ((size_t)NDIM * KDIM / 4) : ((size_t)MDIM * KDIM / 4);

    float pm = 0.0f;
    for (int j = threadIdx.x; j < NPART; j += blockDim.x)
        pm = fmaxf(pm, g_part[which][j]);
    float amax = block_max(pm);
    if (blockIdx.x == 0 && threadIdx.x == 0)
        g_amax[which] = amax;
    __syncthreads();

    uint32_t* __restrict__ q = reinterpret_cast<uint32_t*>(which ? g_qw : g_qin);
    const float s = 448.0f / fmaxf(amax, 1e-12f);
    const float4* x4 = reinterpret_cast<const float4*>(which ? xw : xin);
    const size_t T = (size_t)NPART * 256;
    const size_t gtid = (size_t)blockIdx.x * blockDim.x + threadIdx.x;
    size_t i = gtid;
    if (which == 0) {           // input: L2-resident after amax .ca pass
        for (; i + 3 * T < n4; i += 4 * T) {
            float4 v0 = ldca_f4(&x4[i]);
            float4 v1 = ldca_f4(&x4[i + T]);
            float4 v2 = ldca_f4(&x4[i + 2 * T]);
            float4 v3 = ldca_f4(&x4[i + 3 * T]);
            q[i]         = q4(v0, s);
            q[i + T]     = q4(v1, s);
            q[i + 2 * T] = q4(v2, s);
            q[i + 3 * T] = q4(v3, s);
        }
        for (; i < n4; i += T) q[i] = q4(ldca_f4(&x4[i]), s);
    } else {                    // weight: streaming
        for (; i + 3 * T < n4; i += 4 * T) {
            float4 v0 = ldcs_f4(&x4[i]);
            float4 v1 = ldcs_f4(&x4[i + T]);
            float4 v2 = ldcs_f4(&x4[i + 2 * T]);
            float4 v3 = ldcs_f4(&x4[i + 3 * T]);
            q[i]         = q4(v0, s);
            q[i + T]     = q4(v1, s);
            q[i + 2 * T] = q4(v2, s);
            q[i + 3 * T] = q4(v3, s);
        }
        for (; i < n4; i += T) q[i] = q4(ldcs_f4(&x4[i]), s);
    }
}

// ============================================================================
// Phase 3: FP8 GEMM via mma.sync m16n8k32 (base sm_103 ISA)
//   Grid 2840 (1D): bids [0,2664) full tiles (9 exact waves);
//   bids [2664,2752) = half-K #0 of the last 88 tiles (stores + flag);
//   bids [2752,2840) = half-K #1 (spins on flag, ordered add). Deterministic.
// ============================================================================
__device__ __forceinline__ void issue_stage_load(int mt, int nt, int c,
                                                 uint32_t smem_base, int stage,
                                                 int tid) {
    const uint32_t sA = smem_base + stage * STAGE_BYTES;
    const uint32_t sB = sA + A_BYTES;
    const uint8_t* gA = g_qin + (size_t)mt * BM * KDIM + (size_t)c * BK;
    const uint8_t* gB = g_qw  + (size_t)nt * BN * KDIM + (size_t)c * BK;
    #pragma unroll
    for (int j = 0; j < 4; j++) {                  // A: 128 rows x 8 16B-chunks
        int idx = tid + j * GEMM_THREADS;
        int row = idx >> 3;
        int col = (idx & 7) << 4;
        uint32_t sw = row * 128 + (col ^ ((row & 7) << 4));
        cp_async16(sA + sw, gA + (size_t)row * KDIM + col);
    }
    #pragma unroll
    for (int j = 0; j < 4; j++) {                  // B: 128 rows x 8 16B-chunks
        int idx = tid + j * GEMM_THREADS;
        int row = idx >> 3;
        int col = (idx & 7) << 4;
        uint32_t sw = row * 128 + (col ^ ((row & 7) << 4));
        cp_async16(sB + sw, gB + (size_t)row * KDIM + col);
    }
}

__device__ __forceinline__ void load_frags(uint32_t* af, uint32_t* bf,
                                           uint32_t sbase,
                                           const uint32_t* aRowOff,
                                           const uint32_t* bRowOff,
                                           uint32_t csw) {
    #pragma unroll
    for (int mi = 0; mi < 4; mi++)
        ldmatrix_x4(af[mi * 4 + 0], af[mi * 4 + 1], af[mi * 4 + 2], af[mi * 4 + 3],
                    sbase + aRowOff[mi] + csw);
    #pragma unroll
    for (int bj = 0; bj < 2; bj++)
        ldmatrix_x4(bf[bj * 4 + 0], bf[bj * 4 + 1], bf[bj * 4 + 2], bf[bj * 4 + 3],
                    sbase + bRowOff[bj] + csw);
}

__device__ __forceinline__ void mma_group(float acc[4][4][4],
                                          const uint32_t* af, const uint32_t* bf) {
    #pragma unroll
    for (int mi = 0; mi < 4; mi++)
        #pragma unroll
        for (int ni = 0; ni < 4; ni++) {
            const int bj = ni >> 1, p = ni & 1;
            mma_fp8(acc[mi][ni][0], acc[mi][ni][1],
                    acc[mi][ni][2], acc[mi][ni][3],
                    af[mi * 4 + 0], af[mi * 4 + 1], af[mi * 4 + 2], af[mi * 4 + 3],
                    bf[bj * 4 + p], bf[bj * 4 + 2 + p]);
        }
}

__global__ void __launch_bounds__(GEMM_THREADS, 2)
gemm_kernel(const float* __restrict__ bias, float* __restrict__ out) {
    extern __shared__ char smem[];
    const uint32_t smem_base = smem_u32(smem);
    const int tid  = threadIdx.x;
    const int wid  = tid >> 5;
    const int lane = tid & 31;
    const int wm = wid >> 2;        // 0..1  -> M offset wm*64
    const int wn = wid & 3;         // 0..3  -> N offset wn*32
    const int bid = blockIdx.x;

    // Tile / split-K decode
    int T, c0, c1, mode;            // mode: 0 full, 1 half-lo, 2 half-hi
    if (bid < FULL_TILES)              { T = bid; c0 = 0; c1 = NKCHUNK; mode = 0; }
    else if (bid < TOT_TILES)          { T = bid; c0 = 0; c1 = NKCHUNK / 2; mode = 1; }
    else { T = bid - SPLIT_TILES; c0 = NKCHUNK / 2; c1 = NKCHUNK; mode = 2; }
    const int mt = T / NTILE_N;
    const int nt = T - mt * NTILE_N;
    const int fidx = T - FULL_TILES;   // valid when mode != 0

    const int lrow = lane & 15;
    const int lcolblk = (lane >> 4) << 4;          // 0 or 16 bytes
    const uint32_t lxor = (uint32_t)((lane & 7) << 4);

    uint32_t aRowOff[4], bRowOff[2];
    #pragma unroll
    for (int mi = 0; mi < 4; mi++)
        aRowOff[mi] = (uint32_t)(wm * 64 + mi * 16 + lrow) * 128;
    #pragma unroll
    for (int bj = 0; bj < 2; bj++)
        bRowOff[bj] = (uint32_t)A_BYTES + (uint32_t)(wn * 32 + bj * 16 + lrow) * 128;
    uint32_t colSw[4];
    #pragma unroll
    for (int ks = 0; ks < 4; ks++)
        colSw[ks] = (uint32_t)(ks * 32 + lcolblk) ^ lxor;

    float acc[4][4][4];
    #pragma unroll
    for (int mi = 0; mi < 4; mi++)
        #pragma unroll
        for (int ni = 0; ni < 4; ni++)
            #pragma unroll
            for (int r = 0; r < 4; r++) acc[mi][ni][r] = 0.0f;

    // Prologue: fill stages 0..1 with chunks c0, c0+1
    issue_stage_load(mt, nt, c0, smem_base, 0, tid);
    CP_COMMIT();
    issue_stage_load(mt, nt, c0 + 1, smem_base, 1, tid);
    CP_COMMIT();

    uint32_t afr[2][16], bfr[2][8];   // double-buffered fragments

    int stage = 0, lstage = 2;
    #pragma unroll 1
    for (int c = c0; c < c1; c++) {
        CP_WAIT1();
        __syncthreads();

        if (c + 2 < c1)
            issue_stage_load(mt, nt, c + 2, smem_base, lstage, tid);
        CP_COMMIT();

        const uint32_t sbase = smem_base + stage * STAGE_BYTES;

        load_frags(afr[0], bfr[0], sbase, aRowOff, bRowOff, colSw[0]);
        #pragma unroll
        for (int ks = 0; ks < 4; ks++) {
            const int cur = ks & 1;
            if (ks < 3)
                load_frags(afr[cur ^ 1], bfr[cur ^ 1], sbase,
                           aRowOff, bRowOff, colSw[ks + 1]);
            mma_group(acc, afr[cur], bfr[cur]);
        }

        stage  = (stage  == 2) ? 0 : stage + 1;
        lstage = (lstage == 2) ? 0 : lstage + 1;
    }

    // Epilogue
    const float amax_in = fmaxf(g_amax[0], 1e-12f);
    const float amax_w  = fmaxf(g_amax[1], 1e-12f);
    const float sc = (1.0f / (448.0f / amax_in)) * (1.0f / (448.0f / amax_w));

    const int g = lane >> 2;        // 0..7
    const int t = lane & 3;         // 0..3
    const int mbase = mt * BM + wm * 64 + g;
    const int nbase = nt * BN + wn * 32 + t * 2;

    if (mode != 2) {
        // Full tile or half-lo: out = acc*sc + bias
        #pragma unroll
        for (int mi = 0; mi < 4; mi++) {
            const int m0 = mbase + mi * 16;
            float* o0 = out + (size_t)m0 * NDIM;
            float* o1 = out + (size_t)(m0 + 8) * NDIM;
            #pragma unroll
            for (int ni = 0; ni < 4; ni++) {
                const int n = nbase + ni * 8;
                const float2 bv = *reinterpret_cast<const float2*>(bias + n);
                float2 r0, r1;
                r0.x = fmaf(acc[mi][ni][0], sc, bv.x);
                r0.y = fmaf(acc[mi][ni][1], sc, bv.y);
                r1.x = fmaf(acc[mi][ni][2], sc, bv.x);
                r1.y = fmaf(acc[mi][ni][3], sc, bv.y);
                st_cs_f2(o0 + n, r0);
                st_cs_f2(o1 + n, r1);
            }
        }
        if (mode == 1) {
            // Release: all stores visible, then set flag.
            __threadfence();
            __syncthreads();
            if (tid == 0) atomicExch(&g_flag[fidx], 1);
        }
    } else {
        // Half-hi: wait for half-lo's stores, then ordered add (deterministic).
        if (tid == 0)
            while (atomicAdd(&g_flag[fidx], 0) == 0) __nanosleep(64);
        __syncthreads();
        __threadfence();
        #pragma unroll
        for (int mi = 0; mi < 4; mi++) {
            const int m0 = mbase + mi * 16;
            float* o0 = out + (size_t)m0 * NDIM;
            float* o1 = out + (size_t)(m0 + 8) * NDIM;
            #pragma unroll
            for (int ni = 0; ni < 4; ni++) {
                const int n = nbase + ni * 8;
                float2 v0 = ldcg_f2(o0 + n);
                float2 v1 = ldcg_f2(o1 + n);
                v0.x = fmaf(acc[mi][ni][0], sc, v0.x);
                v0.y = fmaf(acc[mi][ni][1], sc, v0.y);
                v1.x = fmaf(acc[mi][ni][2], sc, v1.x);
                v1.y = fmaf(acc[mi][ni][3], sc, v1.y);
                st_cs_f2(o0 + n, v0);
                st_cs_f2(o1 + n, v1);
            }
        }
    }
}

// ============================================================================
// kernel_launch  (3 launches: amax_both, quant_both, gemm)
// ============================================================================
extern "C" void kernel_launch(void* const* d_in, const int* in_sizes, int n_in,
                              void* d_out, int out_size) {
    const float* inp  = (const float*)d_in[0];
    const float* w    = (const float*)d_in[1];
    const float* bias = (const float*)d_in[2];
    float* out = (float*)d_out;

    cudaFuncSetAttribute(gemm_kernel,
                         cudaFuncAttributeMaxDynamicSharedMemorySize, SMEM_TOTAL);

    dim3 agrid(NPART, 2);
    amax_kernel<<<agrid, 256>>>(inp, w);
    quant_kernel<<<agrid, 256>>>(inp, w);

    gemm_kernel<<<GEMM_GRID, GEMM_THREADS, SMEM_TOTAL>>>(bias, out);
}

// round 16
// speedup vs baseline: 1.0505x; 1.0505x over previous
#include <cuda_runtime.h>
#include <cuda_fp8.h>
#include <cstdint>
#include <cstddef>

// ============================================================================
// Problem constants
// ============================================================================
#define MDIM 4096
#define KDIM 4096
#define NDIM 11008

// GEMM tiling: CTA 128x128, warp 64x32 (2x4 warps), BK=128, 3-stage cp.async
// SMEM/CTA = 96 KB -> 2 CTAs/SM -> 16 warps/SM (4 per SMSP).
// This is the measured optimum: tensor pipe at the legacy-QMMA f32-acc
// ceiling (64.5%), GEMM 944.5us vs 939us dispatch floor. [R14 best]
#define BM 128
#define BN 128
#define BK 128                           // fp8 bytes of K per chunk
#define NKCHUNK (KDIM / BK)              // 32
#define STAGES 3
#define A_BYTES (BM * BK)                // 16384
#define B_BYTES (BN * BK)                // 16384
#define STAGE_BYTES (A_BYTES + B_BYTES)  // 32768
#define SMEM_TOTAL (STAGES * STAGE_BYTES)// 98304
#define GEMM_THREADS 256

#define NPART 2368                        // aux grid size (fixed: partials array)

// ============================================================================
// Scratch (static device globals: allocation-free)
// ============================================================================
__device__ __align__(128) uint8_t g_qin[(size_t)MDIM * KDIM];
__device__ __align__(128) uint8_t g_qw[(size_t)NDIM * KDIM];
__device__ float g_part[2][NPART];       // per-block amax partials
__device__ float g_amax[2];              // final amax (published by quant blk 0)

// ============================================================================
// Small PTX helpers (base sm_103 features only!)
// ============================================================================
__device__ __forceinline__ uint32_t smem_u32(const void* p) {
    uint32_t a;
    asm("{ .reg .u64 t; cvta.to.shared.u64 t, %1; cvt.u32.u64 %0, t; }"
        : "=r"(a) : "l"(p));
    return a;
}

__device__ __forceinline__ void cp_async16(uint32_t dst, const void* src) {
    asm volatile("cp.async.cg.shared.global [%0], [%1], 16;"
                 :: "r"(dst), "l"(src));
}
#define CP_COMMIT() asm volatile("cp.async.commit_group;" ::: "memory")
#define CP_WAIT1()  asm volatile("cp.async.wait_group 1;" ::: "memory")

__device__ __forceinline__ void ldmatrix_x4(uint32_t& r0, uint32_t& r1,
                                            uint32_t& r2, uint32_t& r3,
                                            uint32_t addr) {
    asm volatile("ldmatrix.sync.aligned.m8n8.x4.shared.b16 {%0,%1,%2,%3}, [%4];"
                 : "=r"(r0), "=r"(r1), "=r"(r2), "=r"(r3) : "r"(addr));
}

__device__ __forceinline__ void mma_fp8(float& d0, float& d1, float& d2, float& d3,
                                        uint32_t a0, uint32_t a1, uint32_t a2, uint32_t a3,
                                        uint32_t b0, uint32_t b1) {
    asm volatile(
        "mma.sync.aligned.m16n8k32.row.col.f32.e4m3.e4m3.f32 "
        "{%0,%1,%2,%3}, {%4,%5,%6,%7}, {%8,%9}, {%0,%1,%2,%3};"
        : "+f"(d0), "+f"(d1), "+f"(d2), "+f"(d3)
        : "r"(a0), "r"(a1), "r"(a2), "r"(a3), "r"(b0), "r"(b1));
}

__device__ __forceinline__ void st_cs_f2(float* p, float2 v) {
    asm volatile("st.global.cs.v2.f32 [%0], {%1, %2};"
                 :: "l"(p), "f"(v.x), "f"(v.y) : "memory");
}

__device__ __forceinline__ float4 ldcs_f4(const float4* p) {     // streaming
    float4 v;
    asm volatile("ld.global.cs.v4.f32 {%0,%1,%2,%3}, [%4];"
                 : "=f"(v.x), "=f"(v.y), "=f"(v.z), "=f"(v.w) : "l"(p));
    return v;
}

__device__ __forceinline__ float4 ldca_f4(const float4* p) {     // caching
    float4 v;
    asm volatile("ld.global.ca.v4.f32 {%0,%1,%2,%3}, [%4];"
                 : "=f"(v.x), "=f"(v.y), "=f"(v.z), "=f"(v.w) : "l"(p));
    return v;
}

// ============================================================================
// Block-wide max reduction (order-independent: fmax is assoc/commutative)
// ============================================================================
__device__ __forceinline__ float block_max(float m) {
    #pragma unroll
    for (int o = 16; o; o >>= 1) m = fmaxf(m, __shfl_xor_sync(0xffffffffu, m, o));
    __shared__ float red[8];
    if ((threadIdx.x & 31) == 0) red[threadIdx.x >> 5] = m;
    __syncthreads();
    float r = red[0];
    #pragma unroll
    for (int w = 1; w < 8; w++) r = fmaxf(r, red[w]);
    return r;
}

// ============================================================================
// Phase 1: per-tensor amax -> per-block partials (one launch, gridDim.y=2)
//   Input read .ca (stays L2-resident for quant_in); weight .cs (streaming).
// ============================================================================
__device__ __forceinline__ float amax4(float4 v) {
    return fmaxf(fmaxf(fabsf(v.x), fabsf(v.y)), fmaxf(fabsf(v.z), fabsf(v.w)));
}

template <int CACHED>
__device__ __forceinline__ void amax_body(const float4* x4, size_t n4, int which) {
    const size_t T = (size_t)NPART * 256;
    const size_t gtid = (size_t)blockIdx.x * blockDim.x + threadIdx.x;
    float m[8];
    #pragma unroll
    for (int k = 0; k < 8; k++) m[k] = 0.0f;
    size_t i = gtid;
    for (; i + 7 * T < n4; i += 8 * T) {
        #pragma unroll
        for (int k = 0; k < 8; k++) {
            float4 v = CACHED ? ldca_f4(&x4[i + k * T]) : ldcs_f4(&x4[i + k * T]);
            m[k] = fmaxf(m[k], amax4(v));
        }
    }
    for (; i < n4; i += T)
        m[0] = fmaxf(m[0], amax4(CACHED ? ldca_f4(&x4[i]) : ldcs_f4(&x4[i])));
    float mm = fmaxf(fmaxf(fmaxf(m[0], m[1]), fmaxf(m[2], m[3])),
                     fmaxf(fmaxf(m[4], m[5]), fmaxf(m[6], m[7])));
    mm = block_max(mm);
    if (threadIdx.x == 0) g_part[which][blockIdx.x] = mm;
}

__global__ void amax_kernel(const float* __restrict__ xin,
                            const float* __restrict__ xw) {
    if (blockIdx.y == 0)
        amax_body<1>(reinterpret_cast<const float4*>(xin),
                     (size_t)MDIM * KDIM / 4, 0);
    else
        amax_body<0>(reinterpret_cast<const float4*>(xw),
                     (size_t)NDIM * KDIM / 4, 1);
}

// ============================================================================
// Phase 2: quantize BOTH tensors in ONE launch (gridDim.y selects tensor).
//   Input path: .ca loads (L2-resident after amax); weight path: .cs.
//   The short input job overlaps under the long weight job.
// ============================================================================
__device__ __forceinline__ uint32_t q4(float4 v, float s) {
    float a0 = fminf(fmaxf(v.x * s, -448.0f), 448.0f);
    float a1 = fminf(fmaxf(v.y * s, -448.0f), 448.0f);
    float a2 = fminf(fmaxf(v.z * s, -448.0f), 448.0f);
    float a3 = fminf(fmaxf(v.w * s, -448.0f), 448.0f);
    uint32_t b0 = __nv_cvt_float_to_fp8(a0, __NV_SATFINITE, __NV_E4M3);
    uint32_t b1 = __nv_cvt_float_to_fp8(a1, __NV_SATFINITE, __NV_E4M3);
    uint32_t b2 = __nv_cvt_float_to_fp8(a2, __NV_SATFINITE, __NV_E4M3);
    uint32_t b3 = __nv_cvt_float_to_fp8(a3, __NV_SATFINITE, __NV_E4M3);
    return b0 | (b1 << 8) | (b2 << 16) | (b3 << 24);
}

__global__ void quant_kernel(const float* __restrict__ xin,
                             const float* __restrict__ xw) {
    const int which = blockIdx.y;
    const size_t n4 = which ? ((size_t)NDIM * KDIM / 4) : ((size_t)MDIM * KDIM / 4);

    float pm = 0.0f;
    for (int j = threadIdx.x; j < NPART; j += blockDim.x)
        pm = fmaxf(pm, g_part[which][j]);
    float amax = block_max(pm);
    if (blockIdx.x == 0 && threadIdx.x == 0)
        g_amax[which] = amax;
    __syncthreads();

    uint32_t* __restrict__ q = reinterpret_cast<uint32_t*>(which ? g_qw : g_qin);
    const float s = 448.0f / fmaxf(amax, 1e-12f);
    const float4* x4 = reinterpret_cast<const float4*>(which ? xw : xin);
    const size_t T = (size_t)NPART * 256;
    const size_t gtid = (size_t)blockIdx.x * blockDim.x + threadIdx.x;
    size_t i = gtid;
    if (which == 0) {           // input: L2-resident after amax .ca pass
        for (; i + 3 * T < n4; i += 4 * T) {
            float4 v0 = ldca_f4(&x4[i]);
            float4 v1 = ldca_f4(&x4[i + T]);
            float4 v2 = ldca_f4(&x4[i + 2 * T]);
            float4 v3 = ldca_f4(&x4[i + 3 * T]);
            q[i]         = q4(v0, s);
            q[i + T]     = q4(v1, s);
            q[i + 2 * T] = q4(v2, s);
            q[i + 3 * T] = q4(v3, s);
        }
        for (; i < n4; i += T) q[i] = q4(ldca_f4(&x4[i]), s);
    } else {                    // weight: streaming
        for (; i + 3 * T < n4; i += 4 * T) {
            float4 v0 = ldcs_f4(&x4[i]);
            float4 v1 = ldcs_f4(&x4[i + T]);
            float4 v2 = ldcs_f4(&x4[i + 2 * T]);
            float4 v3 = ldcs_f4(&x4[i + 3 * T]);
            q[i]         = q4(v0, s);
            q[i + T]     = q4(v1, s);
            q[i + 2 * T] = q4(v2, s);
            q[i + 3 * T] = q4(v3, s);
        }
        for (; i < n4; i += T) q[i] = q4(ldcs_f4(&x4[i]), s);
    }
}

// ============================================================================
// Phase 3: FP8 GEMM via mma.sync m16n8k32 (base sm_103 ISA)  [R12/R14 best]
//   CTA 128x128, 3-stage cp.async, SW128 swizzle, warp 64x32, 2 CTAs/SM,
//   ks-level fragment double-buffering. Grid (86, 32), natural waves
//   (continuous work-stealing dispatch balances the 9.3-wave grid to within
//   ~5us of the perfect-balance floor — R15 split-K experiment proved this).
// ============================================================================
__device__ __forceinline__ void issue_stage_load(int mt, int nt, int c,
                                                 uint32_t smem_base, int stage,
                                                 int tid) {
    const uint32_t sA = smem_base + stage * STAGE_BYTES;
    const uint32_t sB = sA + A_BYTES;
    const uint8_t* gA = g_qin + (size_t)mt * BM * KDIM + (size_t)c * BK;
    const uint8_t* gB = g_qw  + (size_t)nt * BN * KDIM + (size_t)c * BK;
    #pragma unroll
    for (int j = 0; j < 4; j++) {                  // A: 128 rows x 8 16B-chunks
        int idx = tid + j * GEMM_THREADS;
        int row = idx >> 3;
        int col = (idx & 7) << 4;
        uint32_t sw = row * 128 + (col ^ ((row & 7) << 4));
        cp_async16(sA + sw, gA + (size_t)row * KDIM + col);
    }
    #pragma unroll
    for (int j = 0; j < 4; j++) {                  // B: 128 rows x 8 16B-chunks
        int idx = tid + j * GEMM_THREADS;
        int row = idx >> 3;
        int col = (idx & 7) << 4;
        uint32_t sw = row * 128 + (col ^ ((row & 7) << 4));
        cp_async16(sB + sw, gB + (size_t)row * KDIM + col);
    }
}

__device__ __forceinline__ void load_frags(uint32_t* af, uint32_t* bf,
                                           uint32_t sbase,
                                           const uint32_t* aRowOff,
                                           const uint32_t* bRowOff,
                                           uint32_t csw) {
    #pragma unroll
    for (int mi = 0; mi < 4; mi++)
        ldmatrix_x4(af[mi * 4 + 0], af[mi * 4 + 1], af[mi * 4 + 2], af[mi * 4 + 3],
                    sbase + aRowOff[mi] + csw);
    #pragma unroll
    for (int bj = 0; bj < 2; bj++)
        ldmatrix_x4(bf[bj * 4 + 0], bf[bj * 4 + 1], bf[bj * 4 + 2], bf[bj * 4 + 3],
                    sbase + bRowOff[bj] + csw);
}

__device__ __forceinline__ void mma_group(float acc[4][4][4],
                                          const uint32_t* af, const uint32_t* bf) {
    #pragma unroll
    for (int mi = 0; mi < 4; mi++)
        #pragma unroll
        for (int ni = 0; ni < 4; ni++) {
            const int bj = ni >> 1, p = ni & 1;
            mma_fp8(acc[mi][ni][0], acc[mi][ni][1],
                    acc[mi][ni][2], acc[mi][ni][3],
                    af[mi * 4 + 0], af[mi * 4 + 1], af[mi * 4 + 2], af[mi * 4 + 3],
                    bf[bj * 4 + p], bf[bj * 4 + 2 + p]);
        }
}

__global__ void __launch_bounds__(GEMM_THREADS, 2)
gemm_kernel(const float* __restrict__ bias, float* __restrict__ out) {
    extern __shared__ char smem[];
    const uint32_t smem_base = smem_u32(smem);
    const int tid  = threadIdx.x;
    const int wid  = tid >> 5;
    const int lane = tid & 31;
    const int wm = wid >> 2;        // 0..1  -> M offset wm*64
    const int wn = wid & 3;         // 0..3  -> N offset wn*32
    const int nt = blockIdx.x;      // 0..85
    const int mt = blockIdx.y;      // 0..31

    const int lrow = lane & 15;
    const int lcolblk = (lane >> 4) << 4;          // 0 or 16 bytes
    const uint32_t lxor = (uint32_t)((lane & 7) << 4);

    uint32_t aRowOff[4], bRowOff[2];
    #pragma unroll
    for (int mi = 0; mi < 4; mi++)
        aRowOff[mi] = (uint32_t)(wm * 64 + mi * 16 + lrow) * 128;
    #pragma unroll
    for (int bj = 0; bj < 2; bj++)
        bRowOff[bj] = (uint32_t)A_BYTES + (uint32_t)(wn * 32 + bj * 16 + lrow) * 128;
    uint32_t colSw[4];
    #pragma unroll
    for (int ks = 0; ks < 4; ks++)
        colSw[ks] = (uint32_t)(ks * 32 + lcolblk) ^ lxor;

    float acc[4][4][4];
    #pragma unroll
    for (int mi = 0; mi < 4; mi++)
        #pragma unroll
        for (int ni = 0; ni < 4; ni++)
            #pragma unroll
            for (int r = 0; r < 4; r++) acc[mi][ni][r] = 0.0f;

    // Prologue: fill stages 0..1
    issue_stage_load(mt, nt, 0, smem_base, 0, tid);
    CP_COMMIT();
    issue_stage_load(mt, nt, 1, smem_base, 1, tid);
    CP_COMMIT();

    uint32_t afr[2][16], bfr[2][8];   // double-buffered fragments

    int stage = 0;          // stage holding chunk c
    int lstage = 2;         // stage to load into (chunk c+2)
    #pragma unroll 1
    for (int c = 0; c < NKCHUNK; c++) {
        CP_WAIT1();
        __syncthreads();

        // Refill: chunk c+2 into the stage freed by chunk c-1 (safe: the
        // sync above ordered all warps past iteration c-1's compute).
        if (c + 2 < NKCHUNK)
            issue_stage_load(mt, nt, c + 2, smem_base, lstage, tid);
        CP_COMMIT();

        const uint32_t sbase = smem_base + stage * STAGE_BYTES;

        // Software-pipelined ks loop: LDSM(ks+1) issues before MMA(ks).
        load_frags(afr[0], bfr[0], sbase, aRowOff, bRowOff, colSw[0]);
        #pragma unroll
        for (int ks = 0; ks < 4; ks++) {
            const int cur = ks & 1;
            if (ks < 3)
                load_frags(afr[cur ^ 1], bfr[cur ^ 1], sbase,
                           aRowOff, bRowOff, colSw[ks + 1]);
            mma_group(acc, afr[cur], bfr[cur]);
        }

        stage  = (stage  == 2) ? 0 : stage + 1;
        lstage = (lstage == 2) ? 0 : lstage + 1;
    }

    // Epilogue: out = acc * (amax_in/448)*(amax_w/448) + bias  (streaming)
    const float amax_in = fmaxf(g_amax[0], 1e-12f);
    const float amax_w  = fmaxf(g_amax[1], 1e-12f);
    const float sc = (1.0f / (448.0f / amax_in)) * (1.0f / (448.0f / amax_w));

    const int g = lane >> 2;        // 0..7
    const int t = lane & 3;         // 0..3
    const int mbase = mt * BM + wm * 64 + g;
    const int nbase = nt * BN + wn * 32 + t * 2;

    #pragma unroll
    for (int mi = 0; mi < 4; mi++) {
        const int m0 = mbase + mi * 16;
        float* o0 = out + (size_t)m0 * NDIM;
        float* o1 = out + (size_t)(m0 + 8) * NDIM;
        #pragma unroll
        for (int ni = 0; ni < 4; ni++) {
            const int n = nbase + ni * 8;
            const float2 bv = *reinterpret_cast<const float2*>(bias + n);
            float2 r0, r1;
            r0.x = fmaf(acc[mi][ni][0], sc, bv.x);
            r0.y = fmaf(acc[mi][ni][1], sc, bv.y);
            r1.x = fmaf(acc[mi][ni][2], sc, bv.x);
            r1.y = fmaf(acc[mi][ni][3], sc, bv.y);
            st_cs_f2(o0 + n, r0);
            st_cs_f2(o1 + n, r1);
        }
    }
}

// ============================================================================
// kernel_launch  (3 launches: amax_both, quant_both, gemm)
// ============================================================================
extern "C" void kernel_launch(void* const* d_in, const int* in_sizes, int n_in,
                              void* d_out, int out_size) {
    const float* inp  = (const float*)d_in[0];
    const float* w    = (const float*)d_in[1];
    const float* bias = (const float*)d_in[2];
    float* out = (float*)d_out;

    cudaFuncSetAttribute(gemm_kernel,
                         cudaFuncAttributeMaxDynamicSharedMemorySize, SMEM_TOTAL);

    dim3 agrid(NPART, 2);
    amax_kernel<<<agrid, 256>>>(inp, w);
    quant_kernel<<<agrid, 256>>>(inp, w);

    dim3 grid(NDIM / BN, MDIM / BM);   // (86, 32)
    gemm_kernel<<<grid, GEMM_THREADS, SMEM_TOTAL>>>(bias, out);
}